// round 2
// baseline (speedup 1.0000x reference)
#include <cuda_runtime.h>
#include <stdint.h>

#define H     128
#define CIN   64
#define NNODE 512
#define BATCH 2

#define ESTRIDE 132   // uint32 stride for E tile (conflict-free A-frag reads)
#define WSTRIDE 136   // uint32 stride for weight tiles (conflict-free B-frag reads)

// smem layout (bytes)
#define OFF_ES   0
#define SZ_ES    (128 * ESTRIDE * 4)             // 67584
#define OFF_W2   (OFF_ES + SZ_ES)                // 67584
#define SZ_W     (128 * WSTRIDE * 4)             // 69632
#define OFF_W3   (OFF_W2 + SZ_W)                 // 137216
#define OFF_OUTS (OFF_W3 + SZ_W)                 // 206848
#define OFF_BC2  (OFF_OUTS + 512)                // 207360
#define OFF_BC3  (OFF_BC2 + 512)                 // 207872
#define OFF_WO   (OFF_BC3 + 512)                 // 208384
#define SMEM_BYTES (OFF_WO + 512)                // 208896

// scratch: u[b,n,k] = (relu-MLP h2)[b,n,:] @ Wc1
__device__ float g_U[BATCH * NNODE * H];

// ---------------------------------------------------------------------------
// helpers
// ---------------------------------------------------------------------------
__device__ __forceinline__ uint32_t f2tf32(float f) {
    uint32_t r;
    asm("cvt.rna.tf32.f32 %0, %1;" : "=r"(r) : "f"(f));
    return r;
}

__device__ __forceinline__ void mma_tf32(float c[4], const uint32_t a[4],
                                         uint32_t b0, uint32_t b1) {
    asm volatile(
        "mma.sync.aligned.m16n8k8.row.col.f32.tf32.tf32.f32 "
        "{%0,%1,%2,%3}, {%4,%5,%6,%7}, {%8,%9}, {%0,%1,%2,%3};"
        : "+f"(c[0]), "+f"(c[1]), "+f"(c[2]), "+f"(c[3])
        : "r"(a[0]), "r"(a[1]), "r"(a[2]), "r"(a[3]), "r"(b0), "r"(b1));
}

// 128x128x128 GEMM: acc[2][8][4] += Es(128xK tf32) @ Ws(KxN tf32)
__device__ __forceinline__ void gemm128(const uint32_t* __restrict__ Es,
                                        const uint32_t* __restrict__ Ws,
                                        float acc[2][8][4],
                                        int m_base, int n_base, int qid, int tq) {
#pragma unroll 4
    for (int k0 = 0; k0 < H; k0 += 8) {
        uint32_t a[2][4];
#pragma unroll
        for (int mt = 0; mt < 2; mt++) {
            const uint32_t* er = Es + (m_base + mt * 16 + qid) * ESTRIDE + k0 + tq;
            a[mt][0] = er[0];
            a[mt][1] = er[8 * ESTRIDE];
            a[mt][2] = er[4];
            a[mt][3] = er[8 * ESTRIDE + 4];
        }
        const uint32_t* wr = Ws + (k0 + tq) * WSTRIDE + n_base + qid;
#pragma unroll
        for (int nt = 0; nt < 8; nt++) {
            uint32_t b0 = wr[nt * 8];
            uint32_t b1 = wr[4 * WSTRIDE + nt * 8];
            mma_tf32(acc[0][nt], a[0], b0, b1);
            mma_tf32(acc[1][nt], a[1], b0, b1);
        }
    }
}

// ---------------------------------------------------------------------------
// stage 1: node MLP + u = h2 @ Wc1   (fp32 exact, tiny)
// ---------------------------------------------------------------------------
#define S1_NODES 8
__global__ __launch_bounds__(128) void stage1_kernel(
    const float* __restrict__ x,
    const float* __restrict__ Wa, const float* __restrict__ ba,
    const float* __restrict__ Wb, const float* __restrict__ bb,
    const float* __restrict__ Wc1) {
    __shared__ float xs[S1_NODES][CIN];
    __shared__ float h1s[S1_NODES][H + 4];
    __shared__ float h2s[S1_NODES][H + 4];
    int tid = threadIdx.x;
    int node0 = blockIdx.x * S1_NODES;

    for (int idx = tid; idx < S1_NODES * CIN; idx += 128)
        xs[idx / CIN][idx % CIN] = x[node0 * CIN + idx];
    __syncthreads();

    int k = tid;
    float acc[S1_NODES];
#pragma unroll
    for (int m = 0; m < S1_NODES; m++) acc[m] = ba[k];
#pragma unroll 8
    for (int c = 0; c < CIN; c++) {
        float w = Wa[c * H + k];
#pragma unroll
        for (int m = 0; m < S1_NODES; m++) acc[m] += xs[m][c] * w;
    }
#pragma unroll
    for (int m = 0; m < S1_NODES; m++) h1s[m][k] = fmaxf(acc[m], 0.f);
    __syncthreads();

#pragma unroll
    for (int m = 0; m < S1_NODES; m++) acc[m] = bb[k];
#pragma unroll 8
    for (int c = 0; c < H; c++) {
        float w = Wb[c * H + k];
#pragma unroll
        for (int m = 0; m < S1_NODES; m++) acc[m] += h1s[m][c] * w;
    }
#pragma unroll
    for (int m = 0; m < S1_NODES; m++) h2s[m][k] = fmaxf(acc[m], 0.f);
    __syncthreads();

#pragma unroll
    for (int m = 0; m < S1_NODES; m++) acc[m] = 0.f;
#pragma unroll 8
    for (int c = 0; c < H; c++) {
        float w = Wc1[c * H + k];
#pragma unroll
        for (int m = 0; m < S1_NODES; m++) acc[m] += h2s[m][c] * w;
    }
#pragma unroll
    for (int m = 0; m < S1_NODES; m++) g_U[(node0 + m) * H + k] = acc[m];
}

// ---------------------------------------------------------------------------
// stage 2: per-edge MLP via tf32 mma, persistent blocks
//   tile = (b, i, 128 consecutive j). 4096 tiles total.
// ---------------------------------------------------------------------------
__global__ __launch_bounds__(256, 1) void stage2_kernel(
    const float* __restrict__ bc1,
    const float* __restrict__ Wc2, const float* __restrict__ bc2,
    const float* __restrict__ Wc3, const float* __restrict__ bc3,
    const float* __restrict__ Wo, const float* __restrict__ bo,
    float* __restrict__ out, int ntiles) {
    extern __shared__ unsigned char smem[];
    uint32_t* Es  = (uint32_t*)(smem + OFF_ES);
    uint32_t* W2s = (uint32_t*)(smem + OFF_W2);
    uint32_t* W3s = (uint32_t*)(smem + OFF_W3);
    float* outs = (float*)(smem + OFF_OUTS);
    float* bc2s = (float*)(smem + OFF_BC2);
    float* bc3s = (float*)(smem + OFF_BC3);
    float* wos  = (float*)(smem + OFF_WO);

    int tid = threadIdx.x;

    // one-time per block: stage weights into smem as tf32
    for (int idx = tid; idx < H * H; idx += 256) {
        int r = idx >> 7, c = idx & 127;
        W2s[r * WSTRIDE + c] = f2tf32(Wc2[idx]);
        W3s[r * WSTRIDE + c] = f2tf32(Wc3[idx]);
    }
    if (tid < H) {
        bc2s[tid] = bc2[tid];
        bc3s[tid] = bc3[tid];
        wos[tid]  = Wo[tid];
    }
    float bo_v = bo[0];
    int col = tid & 127;        // column this thread owns in E1 fill
    float bc1_r = bc1[col];
    __syncthreads();

    int warp = tid >> 5, lane = tid & 31;
    int wm = warp >> 1, wn = warp & 1;
    int m_base = wm * 32, n_base = wn * 64;
    int qid = lane >> 2, tq = lane & 3;   // groupID, threadID-in-group
    int r0 = tid >> 7;                    // 0/1 for E1 fill

    for (int t = blockIdx.x; t < ntiles; t += gridDim.x) {
        int jt = t & 3;
        int i  = (t >> 2) & (NNODE - 1);
        int b  = t >> 11;
        int j0 = jt << 7;
        const float* Ub = g_U + (size_t)b * NNODE * H;
        float ui = Ub[i * H + col];

        // E1[j,k] = ReLU(u[j,k] - u[i,k] + bc1[k])  -> tf32 in smem
#pragma unroll 8
        for (int it = 0; it < 64; it++) {
            int jj = r0 + 2 * it;
            float v = Ub[(j0 + jj) * H + col] - ui + bc1_r;
            Es[jj * ESTRIDE + col] = f2tf32(fmaxf(v, 0.f));
        }
        __syncthreads();

        // GEMM1: Z2 = E1 @ Wc2
        float acc[2][8][4];
#pragma unroll
        for (int mt = 0; mt < 2; mt++)
#pragma unroll
            for (int nt = 0; nt < 8; nt++)
#pragma unroll
                for (int q = 0; q < 4; q++) acc[mt][nt][q] = 0.f;
        gemm128(Es, W2s, acc, m_base, n_base, qid, tq);
        __syncthreads();  // everyone done reading E1

        // E2 = ReLU(Z2 + bc2) -> tf32 back into Es; reset row accumulators
#pragma unroll
        for (int mt = 0; mt < 2; mt++) {
            int r = m_base + mt * 16 + qid;
#pragma unroll
            for (int nt = 0; nt < 8; nt++) {
                int n = n_base + nt * 8 + 2 * tq;
                Es[r * ESTRIDE + n]           = f2tf32(fmaxf(acc[mt][nt][0] + bc2s[n], 0.f));
                Es[r * ESTRIDE + n + 1]       = f2tf32(fmaxf(acc[mt][nt][1] + bc2s[n + 1], 0.f));
                Es[(r + 8) * ESTRIDE + n]     = f2tf32(fmaxf(acc[mt][nt][2] + bc2s[n], 0.f));
                Es[(r + 8) * ESTRIDE + n + 1] = f2tf32(fmaxf(acc[mt][nt][3] + bc2s[n + 1], 0.f));
            }
        }
        if (tid < H) outs[tid] = bo_v;
        __syncthreads();

        // GEMM2: Z3 = E2 @ Wc3
#pragma unroll
        for (int mt = 0; mt < 2; mt++)
#pragma unroll
            for (int nt = 0; nt < 8; nt++)
#pragma unroll
                for (int q = 0; q < 4; q++) acc[mt][nt][q] = 0.f;
        gemm128(Es, W3s, acc, m_base, n_base, qid, tq);

        // epilogue: out_row += sum_n ReLU(Z3 + bc3) * Wo
#pragma unroll
        for (int mt = 0; mt < 2; mt++) {
            float s0 = 0.f, s1 = 0.f;
#pragma unroll
            for (int nt = 0; nt < 8; nt++) {
                int n = n_base + nt * 8 + 2 * tq;
                s0 += fmaxf(acc[mt][nt][0] + bc3s[n], 0.f) * wos[n]
                    + fmaxf(acc[mt][nt][1] + bc3s[n + 1], 0.f) * wos[n + 1];
                s1 += fmaxf(acc[mt][nt][2] + bc3s[n], 0.f) * wos[n]
                    + fmaxf(acc[mt][nt][3] + bc3s[n + 1], 0.f) * wos[n + 1];
            }
            s0 += __shfl_xor_sync(0xffffffffu, s0, 1);
            s0 += __shfl_xor_sync(0xffffffffu, s0, 2);
            s1 += __shfl_xor_sync(0xffffffffu, s1, 1);
            s1 += __shfl_xor_sync(0xffffffffu, s1, 2);
            if (tq == 0) {
                atomicAdd(&outs[m_base + mt * 16 + qid], s0);
                atomicAdd(&outs[m_base + mt * 16 + qid + 8], s1);
            }
        }
        __syncthreads();  // atomics visible; GEMM2 smem reads done

        if (tid < H)
            out[((size_t)b * NNODE + i) * NNODE + j0 + tid] = outs[tid];
        __syncthreads();  // protect outs/Es for next tile
    }
}

// ---------------------------------------------------------------------------
extern "C" void kernel_launch(void* const* d_in, const int* in_sizes, int n_in,
                              void* d_out, int out_size) {
    const float* x   = (const float*)d_in[0];
    const float* Wa  = (const float*)d_in[1];
    const float* ba  = (const float*)d_in[2];
    const float* Wb  = (const float*)d_in[3];
    const float* bb  = (const float*)d_in[4];
    const float* Wc1 = (const float*)d_in[5];
    const float* bc1 = (const float*)d_in[6];
    const float* Wc2 = (const float*)d_in[7];
    const float* bc2 = (const float*)d_in[8];
    const float* Wc3 = (const float*)d_in[9];
    const float* bc3 = (const float*)d_in[10];
    const float* Wo  = (const float*)d_in[11];
    const float* bo  = (const float*)d_in[12];
    float* out = (float*)d_out;

    cudaFuncSetAttribute(stage2_kernel,
                         cudaFuncAttributeMaxDynamicSharedMemorySize, SMEM_BYTES);

    stage1_kernel<<<(BATCH * NNODE) / S1_NODES, 128>>>(x, Wa, ba, Wb, bb, Wc1);

    int ntiles = BATCH * NNODE * (NNODE / 128);  // 4096
    stage2_kernel<<<152, 256, SMEM_BYTES>>>(bc1, Wc2, bc2, Wc3, bc3, Wo, bo,
                                            out, ntiles);
}

// round 3
// speedup vs baseline: 2.0241x; 2.0241x over previous
#include <cuda_runtime.h>
#include <cuda_fp16.h>
#include <stdint.h>

#define H     128
#define CIN   64
#define NNODE 512
#define BATCH 2

// uint32 (=half2) strides, conflict-free per-fragment (see analysis)
#define ESTRIDE 68    // E tile: 128 rows x 64 half2  (row bank phase = qid*4)
#define WSTRIDE 136   // W tile: 64 kpair-rows x 128 n (row bank phase = tq*8)

// smem layout (bytes)
#define OFF_ES   0
#define SZ_ES    (128 * ESTRIDE * 4)             // 34816
#define OFF_W2   (OFF_ES + SZ_ES)                // 34816
#define SZ_W     (64 * WSTRIDE * 4)              // 34816
#define OFF_W3   (OFF_W2 + SZ_W)                 // 69632
#define OFF_OUTS (OFF_W3 + SZ_W)                 // 104448
#define OFF_BC2  (OFF_OUTS + 512)
#define OFF_BC3  (OFF_BC2 + 512)
#define OFF_WO   (OFF_BC3 + 512)
#define SMEM_BYTES (OFF_WO + 512)                // 106496

// scratch: u[b,n,k] = (relu-MLP h2)[b,n,:] @ Wc1
__device__ float g_U[BATCH * NNODE * H];

// ---------------------------------------------------------------------------
__device__ __forceinline__ uint32_t pack2(float a, float b) {
    __half2 h = __floats2half2_rn(a, b);
    return *reinterpret_cast<uint32_t*>(&h);
}

__device__ __forceinline__ void mma_f16(float c[4], const uint32_t a[4],
                                        uint32_t b0, uint32_t b1) {
    asm volatile(
        "mma.sync.aligned.m16n8k16.row.col.f32.f16.f16.f32 "
        "{%0,%1,%2,%3}, {%4,%5,%6,%7}, {%8,%9}, {%0,%1,%2,%3};"
        : "+f"(c[0]), "+f"(c[1]), "+f"(c[2]), "+f"(c[3])
        : "r"(a[0]), "r"(a[1]), "r"(a[2]), "r"(a[3]), "r"(b0), "r"(b1));
}

// 128x128x128 fp16 GEMM: acc += Es(128x128 half) @ Ws(128x128 half)
__device__ __forceinline__ void gemm128h(const uint32_t* __restrict__ Es,
                                         const uint32_t* __restrict__ Ws,
                                         float acc[2][8][4],
                                         int m_base, int n_base, int qid, int tq) {
#pragma unroll
    for (int k0 = 0; k0 < 64; k0 += 8) {   // k0 in half2 units (16 halves/step)
        uint32_t a[2][4];
#pragma unroll
        for (int mt = 0; mt < 2; mt++) {
            const uint32_t* er = Es + (m_base + mt * 16 + qid) * ESTRIDE + k0 + tq;
            a[mt][0] = er[0];
            a[mt][1] = er[8 * ESTRIDE];
            a[mt][2] = er[4];
            a[mt][3] = er[8 * ESTRIDE + 4];
        }
        const uint32_t* wr = Ws + (k0 + tq) * WSTRIDE + n_base + qid;
#pragma unroll
        for (int nt = 0; nt < 8; nt++) {
            uint32_t b0 = wr[nt * 8];
            uint32_t b1 = wr[4 * WSTRIDE + nt * 8];
            mma_f16(acc[0][nt], a[0], b0, b1);
            mma_f16(acc[1][nt], a[1], b0, b1);
        }
    }
}

// ---------------------------------------------------------------------------
// stage 1: node MLP + u = h2 @ Wc1   (fp32 exact, tiny)
// ---------------------------------------------------------------------------
#define S1_NODES 8
__global__ __launch_bounds__(128) void stage1_kernel(
    const float* __restrict__ x,
    const float* __restrict__ Wa, const float* __restrict__ ba,
    const float* __restrict__ Wb, const float* __restrict__ bb,
    const float* __restrict__ Wc1) {
    __shared__ float xs[S1_NODES][CIN];
    __shared__ float h1s[S1_NODES][H + 4];
    __shared__ float h2s[S1_NODES][H + 4];
    int tid = threadIdx.x;
    int node0 = blockIdx.x * S1_NODES;

    for (int idx = tid; idx < S1_NODES * CIN; idx += 128)
        xs[idx / CIN][idx % CIN] = x[node0 * CIN + idx];
    __syncthreads();

    int k = tid;
    float acc[S1_NODES];
#pragma unroll
    for (int m = 0; m < S1_NODES; m++) acc[m] = ba[k];
#pragma unroll 8
    for (int c = 0; c < CIN; c++) {
        float w = Wa[c * H + k];
#pragma unroll
        for (int m = 0; m < S1_NODES; m++) acc[m] += xs[m][c] * w;
    }
#pragma unroll
    for (int m = 0; m < S1_NODES; m++) h1s[m][k] = fmaxf(acc[m], 0.f);
    __syncthreads();

#pragma unroll
    for (int m = 0; m < S1_NODES; m++) acc[m] = bb[k];
#pragma unroll 8
    for (int c = 0; c < H; c++) {
        float w = Wb[c * H + k];
#pragma unroll
        for (int m = 0; m < S1_NODES; m++) acc[m] += h1s[m][c] * w;
    }
#pragma unroll
    for (int m = 0; m < S1_NODES; m++) h2s[m][k] = fmaxf(acc[m], 0.f);
    __syncthreads();

#pragma unroll
    for (int m = 0; m < S1_NODES; m++) acc[m] = 0.f;
#pragma unroll 8
    for (int c = 0; c < H; c++) {
        float w = Wc1[c * H + k];
#pragma unroll
        for (int m = 0; m < S1_NODES; m++) acc[m] += h2s[m][c] * w;
    }
#pragma unroll
    for (int m = 0; m < S1_NODES; m++) g_U[(node0 + m) * H + k] = acc[m];
}

// ---------------------------------------------------------------------------
// stage 2: per-edge MLP via fp16 mma (fp32 accum), 2 CTAs / SM
//   tile = (b, i, 128 consecutive j). 4096 tiles total.
// ---------------------------------------------------------------------------
__global__ __launch_bounds__(256, 2) void stage2_kernel(
    const float* __restrict__ bc1,
    const float* __restrict__ Wc2, const float* __restrict__ bc2,
    const float* __restrict__ Wc3, const float* __restrict__ bc3,
    const float* __restrict__ Wo, const float* __restrict__ bo,
    float* __restrict__ out, int ntiles) {
    extern __shared__ unsigned char smem[];
    uint32_t* Es  = (uint32_t*)(smem + OFF_ES);
    uint32_t* W2s = (uint32_t*)(smem + OFF_W2);
    uint32_t* W3s = (uint32_t*)(smem + OFF_W3);
    float* outs = (float*)(smem + OFF_OUTS);
    float* bc2s = (float*)(smem + OFF_BC2);
    float* bc3s = (float*)(smem + OFF_BC3);
    float* wos  = (float*)(smem + OFF_WO);

    int tid = threadIdx.x;

    // one-time: stage weights as half2 (k-pair packed: x = even k)
    for (int idx = tid; idx < 64 * H; idx += 256) {
        int kp = idx >> 7, n = idx & 127;
        W2s[kp * WSTRIDE + n] = pack2(Wc2[(2 * kp) * H + n], Wc2[(2 * kp + 1) * H + n]);
        W3s[kp * WSTRIDE + n] = pack2(Wc3[(2 * kp) * H + n], Wc3[(2 * kp + 1) * H + n]);
    }
    if (tid < H) {
        bc2s[tid] = bc2[tid];
        bc3s[tid] = bc3[tid];
        wos[tid]  = Wo[tid];
    }
    float bo_v = bo[0];

    int c2 = tid & 63;            // half2 column pair owned in E1 fill
    int r0 = tid >> 6;            // row phase (0..3)
    float2 bc1v = ((const float2*)bc1)[c2];
    __syncthreads();

    int warp = tid >> 5, lane = tid & 31;
    int wm = warp >> 1, wn = warp & 1;
    int m_base = wm * 32, n_base = wn * 64;
    int qid = lane >> 2, tq = lane & 3;

    for (int t = blockIdx.x; t < ntiles; t += gridDim.x) {
        int jt = t & 3;
        int i  = (t >> 2) & (NNODE - 1);
        int b  = t >> 11;
        int j0 = jt << 7;
        const float2* Ub2 = (const float2*)(g_U + (size_t)b * NNODE * H);
        float2 ui = Ub2[i * 64 + c2];

        // E1[j,k] = ReLU(u[j,k] - u[i,k] + bc1[k]) -> half2 in smem
#pragma unroll 8
        for (int it = 0; it < 32; it++) {
            int jj = r0 + 4 * it;
            float2 uv = Ub2[(j0 + jj) * 64 + c2];
            Es[jj * ESTRIDE + c2] = pack2(fmaxf(uv.x - ui.x + bc1v.x, 0.f),
                                          fmaxf(uv.y - ui.y + bc1v.y, 0.f));
        }
        __syncthreads();

        // GEMM1: Z2 = E1 @ Wc2
        float acc[2][8][4];
#pragma unroll
        for (int mt = 0; mt < 2; mt++)
#pragma unroll
            for (int nt = 0; nt < 8; nt++)
#pragma unroll
                for (int q = 0; q < 4; q++) acc[mt][nt][q] = 0.f;
        gemm128h(Es, W2s, acc, m_base, n_base, qid, tq);
        __syncthreads();  // all reads of E1 done

        // E2 = ReLU(Z2 + bc2) -> half2 back into Es
#pragma unroll
        for (int mt = 0; mt < 2; mt++) {
            int r = m_base + mt * 16 + qid;
#pragma unroll
            for (int nt = 0; nt < 8; nt++) {
                int n  = n_base + nt * 8 + 2 * tq;
                int np = n >> 1;   // half2 index (n even)
                Es[r * ESTRIDE + np] =
                    pack2(fmaxf(acc[mt][nt][0] + bc2s[n], 0.f),
                          fmaxf(acc[mt][nt][1] + bc2s[n + 1], 0.f));
                Es[(r + 8) * ESTRIDE + np] =
                    pack2(fmaxf(acc[mt][nt][2] + bc2s[n], 0.f),
                          fmaxf(acc[mt][nt][3] + bc2s[n + 1], 0.f));
            }
        }
        if (tid < H) outs[tid] = bo_v;
        __syncthreads();

        // GEMM2: Z3 = E2 @ Wc3
#pragma unroll
        for (int mt = 0; mt < 2; mt++)
#pragma unroll
            for (int nt = 0; nt < 8; nt++)
#pragma unroll
                for (int q = 0; q < 4; q++) acc[mt][nt][q] = 0.f;
        gemm128h(Es, W3s, acc, m_base, n_base, qid, tq);

        // epilogue: out_row += sum_n ReLU(Z3 + bc3) * Wo
#pragma unroll
        for (int mt = 0; mt < 2; mt++) {
            float s0 = 0.f, s1 = 0.f;
#pragma unroll
            for (int nt = 0; nt < 8; nt++) {
                int n = n_base + nt * 8 + 2 * tq;
                s0 += fmaxf(acc[mt][nt][0] + bc3s[n], 0.f) * wos[n]
                    + fmaxf(acc[mt][nt][1] + bc3s[n + 1], 0.f) * wos[n + 1];
                s1 += fmaxf(acc[mt][nt][2] + bc3s[n], 0.f) * wos[n]
                    + fmaxf(acc[mt][nt][3] + bc3s[n + 1], 0.f) * wos[n + 1];
            }
            s0 += __shfl_xor_sync(0xffffffffu, s0, 1);
            s0 += __shfl_xor_sync(0xffffffffu, s0, 2);
            s1 += __shfl_xor_sync(0xffffffffu, s1, 1);
            s1 += __shfl_xor_sync(0xffffffffu, s1, 2);
            if (tq == 0) {
                atomicAdd(&outs[m_base + mt * 16 + qid], s0);
                atomicAdd(&outs[m_base + mt * 16 + qid + 8], s1);
            }
        }
        __syncthreads();

        if (tid < H)
            out[((size_t)b * NNODE + i) * NNODE + j0 + tid] = outs[tid];
        __syncthreads();
    }
}

// ---------------------------------------------------------------------------
extern "C" void kernel_launch(void* const* d_in, const int* in_sizes, int n_in,
                              void* d_out, int out_size) {
    const float* x   = (const float*)d_in[0];
    const float* Wa  = (const float*)d_in[1];
    const float* ba  = (const float*)d_in[2];
    const float* Wb  = (const float*)d_in[3];
    const float* bb  = (const float*)d_in[4];
    const float* Wc1 = (const float*)d_in[5];
    const float* bc1 = (const float*)d_in[6];
    const float* Wc2 = (const float*)d_in[7];
    const float* bc2 = (const float*)d_in[8];
    const float* Wc3 = (const float*)d_in[9];
    const float* bc3 = (const float*)d_in[10];
    const float* Wo  = (const float*)d_in[11];
    const float* bo  = (const float*)d_in[12];
    float* out = (float*)d_out;

    cudaFuncSetAttribute(stage2_kernel,
                         cudaFuncAttributeMaxDynamicSharedMemorySize, SMEM_BYTES);

    stage1_kernel<<<(BATCH * NNODE) / S1_NODES, 128>>>(x, Wa, ba, Wb, bb, Wc1);

    int ntiles = BATCH * NNODE * (NNODE / 128);  // 4096
    stage2_kernel<<<304, 256, SMEM_BYTES>>>(bc1, Wc2, bc2, Wc3, bc3, Wo, bo,
                                            out, ntiles);
}